// round 2
// baseline (speedup 1.0000x reference)
#include <cuda_runtime.h>
#include <cstdint>

// ---------------------------------------------------------------------------
// Problem constants
// ---------------------------------------------------------------------------
constexpr int BB = 32, CC = 256, HH = 56, WW = 56;
constexpr int HP = 58, WP = 58;                 // padded spatial
constexpr int HWs = HH * WW;                    // 3136
constexpr int CHW = CC * HWs;                   // 802816
constexpr int PIX = BB * HWs;                   // 100352
constexpr int KD  = 2304;                       // Cin * 9
constexpr int TILE_M = 128;
constexpr int TILE_N = 128;
constexpr int NTILES = PIX / TILE_M;            // 784
constexpr int NCHUNK = KD / 64;                 // 36 chunks of 64 int8
constexpr float BN_EPS = 1e-5f;

// smem row stride (bytes) for A/B tiles: 64 data bytes padded to 80 -> the
// (20*row + kgroup) % 32 bank pattern is conflict-free for fragment loads.
constexpr int SSTR = 80;

// ---------------------------------------------------------------------------
// Device scratch (allocation-free: __device__ globals)
// ---------------------------------------------------------------------------
__device__ uint4 g_xa_raw[(size_t)BB * HP * WP * CC / 16];  // int8 padded NHWC, 27.5MB
__device__ uint4 g_wb_raw[(size_t)CC * KD / 16];            // int8 [co][tap*256+ci], 590KB
__device__ float g_y[(size_t)PIX * CC];                     // conv accum (unscaled), NCHW
__device__ float g_scale[CC];
__device__ float g_sum[CC];
__device__ float g_sumsq[CC];
__device__ float g_ab[2 * CC];

#define G_XA ((int8_t*)g_xa_raw)
#define G_WB ((int8_t*)g_wb_raw)

// ---------------------------------------------------------------------------
// IMMA: m16n8k32 s8*s8 -> s32  (baseline PTX, works at .target sm_103)
// ---------------------------------------------------------------------------
__device__ __forceinline__ void mma_s8(int* d, uint32_t a0, uint32_t a1,
                                       uint32_t a2, uint32_t a3,
                                       uint32_t b0, uint32_t b1) {
    asm volatile(
        "mma.sync.aligned.m16n8k32.row.col.s32.s8.s8.s32 "
        "{%0,%1,%2,%3}, {%4,%5,%6,%7}, {%8,%9}, {%0,%1,%2,%3};"
        : "+r"(d[0]), "+r"(d[1]), "+r"(d[2]), "+r"(d[3])
        : "r"(a0), "r"(a1), "r"(a2), "r"(a3), "r"(b0), "r"(b1));
}

// ---------------------------------------------------------------------------
// Kernel: zero BN accumulators
// ---------------------------------------------------------------------------
__global__ void zero_stats_kernel() {
    int t = threadIdx.x;
    if (t < CC) { g_sum[t] = 0.0f; g_sumsq[t] = 0.0f; }
}

// ---------------------------------------------------------------------------
// Kernel: zero padded border of xa (1 border pixel per block, 256 bytes)
// ---------------------------------------------------------------------------
__global__ void border_kernel() {
    int i = blockIdx.x, b = blockIdx.y;
    int h, w;
    if (i < 58)       { h = 0;           w = i; }
    else if (i < 116) { h = 57;          w = i - 58; }
    else if (i < 172) { h = i - 116 + 1; w = 0; }
    else              { h = i - 172 + 1; w = 57; }
    G_XA[(((size_t)(b * HP + h) * WP + w) * CC) + threadIdx.x] = 0;
}

// ---------------------------------------------------------------------------
// Kernel: sign(x), NCHW fp32 -> padded NHWC int8 (smem transpose, packed u32)
// ---------------------------------------------------------------------------
__global__ void sign_transpose_kernel(const float* __restrict__ x) {
    int h = blockIdx.x, b = blockIdx.y;
    __shared__ float tile[64][57];
    int tid = threadIdx.x;
    for (int cb = 0; cb < 4; cb++) {
        for (int idx = tid; idx < 64 * 56; idx += 256) {
            int ci = idx / 56, w = idx - ci * 56;
            tile[ci][w] = x[((size_t)(b * CC + cb * 64 + ci) * HH + h) * WW + w];
        }
        __syncthreads();
        // 56 w-positions x 16 groups of 4 channels -> packed 4-byte stores
        for (int idx = tid; idx < 56 * 16; idx += 256) {
            int w = idx >> 4, g = idx & 15;
            uint32_t packed = 0;
#pragma unroll
            for (int k = 0; k < 4; k++) {
                float v = tile[g * 4 + k][w];
                int s = (v > 0.0f) ? 1 : ((v < 0.0f) ? -1 : 0);
                packed |= (uint32_t)((uint8_t)(int8_t)s) << (k * 8);
            }
            *(uint32_t*)&G_XA[(((size_t)(b * HP + h + 1) * WP + (w + 1)) * CC) +
                              cb * 64 + g * 4] = packed;
        }
        __syncthreads();
    }
}

// ---------------------------------------------------------------------------
// Kernel: weight scale (mean |w| per Cout) + int8 signs [co][tap*256 + ci]
// ---------------------------------------------------------------------------
__global__ void wprep_kernel(const float* __restrict__ w) {
    int o = blockIdx.x, tid = threadIdx.x;
    const float* wp = w + ((size_t)o * CC + tid) * 9;
    float v[9]; float s = 0.0f;
#pragma unroll
    for (int t = 0; t < 9; t++) { v[t] = wp[t]; s += fabsf(v[t]); }
#pragma unroll
    for (int off = 16; off; off >>= 1) s += __shfl_xor_sync(~0u, s, off);
    __shared__ float sh[8];
    if ((tid & 31) == 0) sh[tid >> 5] = s;
    __syncthreads();
    if (tid == 0) {
        float t = 0.0f;
        for (int i = 0; i < 8; i++) t += sh[i];
        g_scale[o] = t / (float)KD;
    }
#pragma unroll
    for (int t = 0; t < 9; t++) {
        float xv = v[t];
        int sg = (xv > 0.0f) ? 1 : ((xv < 0.0f) ? -1 : 0);
        G_WB[(size_t)o * KD + t * 256 + tid] = (int8_t)sg;
    }
}

// ---------------------------------------------------------------------------
// Kernel: implicit-GEMM conv, CTA tile M=128 x N=128, K=2304, int8 IMMA.
// 8 warps: warp (wm = wid&3, wn = wid>>2) computes 32 rows x 64 cols.
// Double-buffered smem, one barrier per K-chunk, BN stats fused in epilogue.
// ---------------------------------------------------------------------------
__global__ __launch_bounds__(256) void gemm_kernel() {
    __shared__ __align__(16) char sA[2][TILE_M * SSTR];
    __shared__ __align__(16) char sB[2][TILE_N * SSTR];

    const int tid = threadIdx.x;
    const int wid = tid >> 5;
    const int lane = tid & 31;
    const int wm = wid & 3;      // m-block of 32 rows
    const int wn = wid >> 2;     // n-block of 64 cols
    const int p0 = blockIdx.x * TILE_M;
    const int n0 = blockIdx.y * TILE_N;

    // staging: thread t loads 32B of row r (A: pixel row, B: cout row)
    const int r = tid >> 1, half = tid & 1;
    int p = p0 + r;
    int b = p / HWs; int hw = p - b * HWs;
    int h = hw / WW; int w = hw - h * WW;
    const int8_t* abase = G_XA + (((size_t)(b * HP + h) * WP + w) * CC) + half * 32;
    const int8_t* bbase = G_WB + (size_t)(n0 + r) * KD + half * 32;
    const int sdst = r * SSTR + half * 32;

    int acc[2][8][4];
#pragma unroll
    for (int mf = 0; mf < 2; mf++)
#pragma unroll
        for (int nf = 0; nf < 8; nf++)
#pragma unroll
            for (int i = 0; i < 4; i++) acc[mf][nf][i] = 0;

    uint4 pf[4];
    auto gload = [&](int kc) {
        int tap = kc >> 2;
        int ci0 = (kc & 3) * 64;
        int kh = tap / 3, kw = tap - 3 * kh;
        const uint4* as = (const uint4*)(abase + ((kh * WP + kw) * CC + ci0));
        pf[0] = as[0]; pf[1] = as[1];
        const uint4* bs = (const uint4*)(bbase + tap * 256 + ci0);
        pf[2] = bs[0]; pf[3] = bs[1];
    };
    auto sstore = [&](int buf) {
        *(uint4*)&sA[buf][sdst]      = pf[0];
        *(uint4*)&sA[buf][sdst + 16] = pf[1];
        *(uint4*)&sB[buf][sdst]      = pf[2];
        *(uint4*)&sB[buf][sdst + 16] = pf[3];
    };

    gload(0); sstore(0);
    __syncthreads();

    for (int kc = 0; kc < NCHUNK; kc++) {
        const int buf = kc & 1;
        const bool hasNext = (kc + 1) < NCHUNK;
        if (hasNext) gload(kc + 1);

        const char* A = sA[buf];
        const char* Bt = sB[buf];
#pragma unroll
        for (int s = 0; s < 2; s++) {
            uint32_t a[2][4];
#pragma unroll
            for (int mf = 0; mf < 2; mf++) {
                int row = wm * 32 + mf * 16 + (lane >> 2);
                int ko = s * 32 + (lane & 3) * 4;
                a[mf][0] = *(const uint32_t*)&A[row * SSTR + ko];
                a[mf][1] = *(const uint32_t*)&A[(row + 8) * SSTR + ko];
                a[mf][2] = *(const uint32_t*)&A[row * SSTR + ko + 16];
                a[mf][3] = *(const uint32_t*)&A[(row + 8) * SSTR + ko + 16];
            }
#pragma unroll
            for (int nf = 0; nf < 8; nf++) {
                int nrow = wn * 64 + nf * 8 + (lane >> 2);
                int ko = s * 32 + (lane & 3) * 4;
                uint32_t b0 = *(const uint32_t*)&Bt[nrow * SSTR + ko];
                uint32_t b1 = *(const uint32_t*)&Bt[nrow * SSTR + ko + 16];
                mma_s8(acc[0][nf], a[0][0], a[0][1], a[0][2], a[0][3], b0, b1);
                mma_s8(acc[1][nf], a[1][0], a[1][1], a[1][2], a[1][3], b0, b1);
            }
        }
        if (hasNext) sstore(buf ^ 1);
        __syncthreads();
    }

    // ---- Epilogue 1: fused BN statistics (per-channel sum / sumsq) ----
    // channel for (nf, j): n0 + wn*64 + nf*8 + 2*(lane&3) + j
    {
#pragma unroll
        for (int nf = 0; nf < 8; nf++) {
#pragma unroll
            for (int j = 0; j < 2; j++) {
                float s = 0.0f, s2 = 0.0f;
#pragma unroll
                for (int mf = 0; mf < 2; mf++) {
#pragma unroll
                    for (int rh = 0; rh < 2; rh++) {
                        float v = (float)acc[mf][nf][rh * 2 + j];
                        s += v; s2 += v * v;
                    }
                }
#pragma unroll
                for (int o = 4; o < 32; o <<= 1) {
                    s  += __shfl_xor_sync(~0u, s, o);
                    s2 += __shfl_xor_sync(~0u, s2, o);
                }
                if (lane < 4) {
                    int c = n0 + wn * 64 + nf * 8 + 2 * lane + j;
                    atomicAdd(&g_sum[c], s);
                    atomicAdd(&g_sumsq[c], s2);
                }
            }
        }
    }

    // ---- Epilogue 2: write conv accumulators to g_y (NCHW, fp32) ----
#pragma unroll
    for (int mf = 0; mf < 2; mf++) {
#pragma unroll
        for (int rh = 0; rh < 2; rh++) {
            int p2 = p0 + wm * 32 + mf * 16 + (lane >> 2) + rh * 8;
            int b2 = p2 / HWs; int hw2 = p2 - b2 * HWs;
            float* yd = g_y + (size_t)b2 * CHW + hw2;
#pragma unroll
            for (int nf = 0; nf < 8; nf++) {
                int c = n0 + wn * 64 + nf * 8 + 2 * (lane & 3);
                yd[(size_t)c * HWs]       = (float)acc[mf][nf][rh * 2 + 0];
                yd[(size_t)(c + 1) * HWs] = (float)acc[mf][nf][rh * 2 + 1];
            }
        }
    }
}

// ---------------------------------------------------------------------------
// Kernel: BN affine coefficients (weight scale folded in exactly)
// out = gamma*(s*u - s*mu)*rsqrt(s^2*var_u + eps) + beta = A*u + B
// ---------------------------------------------------------------------------
__global__ void coeff_kernel(const float* __restrict__ gamma, const float* __restrict__ beta) {
    int c = threadIdx.x;
    float n  = (float)PIX;
    float mu = g_sum[c] / n;
    float vu = g_sumsq[c] / n - mu * mu;
    float sc = g_scale[c];
    float A  = gamma[c] * sc * rsqrtf(sc * sc * vu + BN_EPS);
    g_ab[c]      = A;
    g_ab[CC + c] = beta[c] - A * mu;
}

// ---------------------------------------------------------------------------
// Kernel: out = relu(A*u + B)   (vectorized, NCHW)
// ---------------------------------------------------------------------------
__global__ void finalize_kernel(float* __restrict__ out) {
    size_t n4 = (size_t)PIX * CC / 4;
    for (size_t i = (size_t)blockIdx.x * blockDim.x + threadIdx.x; i < n4;
         i += (size_t)gridDim.x * blockDim.x) {
        size_t j = i * 4;
        int c = (int)((j / HWs) & 255);
        float A = g_ab[c], Bv = g_ab[CC + c];
        float4 v = ((const float4*)g_y)[i];
        float4 o;
        o.x = fmaxf(fmaf(v.x, A, Bv), 0.0f);
        o.y = fmaxf(fmaf(v.y, A, Bv), 0.0f);
        o.z = fmaxf(fmaf(v.z, A, Bv), 0.0f);
        o.w = fmaxf(fmaf(v.w, A, Bv), 0.0f);
        ((float4*)out)[i] = o;
    }
}

// ---------------------------------------------------------------------------
// Launch
// ---------------------------------------------------------------------------
extern "C" void kernel_launch(void* const* d_in, const int* in_sizes, int n_in,
                              void* d_out, int out_size) {
    (void)in_sizes; (void)n_in; (void)out_size;
    const float* x     = (const float*)d_in[0];
    const float* wt    = (const float*)d_in[1];
    const float* gamma = (const float*)d_in[2];
    const float* beta  = (const float*)d_in[3];
    float* out = (float*)d_out;

    zero_stats_kernel<<<1, 256>>>();
    border_kernel<<<dim3(228, 32), 256>>>();
    sign_transpose_kernel<<<dim3(56, 32), 256>>>(x);
    wprep_kernel<<<256, 256>>>(wt);
    gemm_kernel<<<dim3(NTILES, 2), 256>>>();
    coeff_kernel<<<1, 256>>>(gamma, beta);
    finalize_kernel<<<8192, 256>>>(out);
}